// round 10
// baseline (speedup 1.0000x reference)
#include <cuda_runtime.h>
#include <cuda_bf16.h>
#include <cstdint>

#define NB   16
#define NN   4096
#define NS   1024
#define NK   32
#define NC   64
#define NOUT 128
#define CIN  67          // 3 + 64

// kNN index scratch (static device global; allocation is forbidden)
__device__ int g_idx[NB * NS * NK];

// ---- packed f32x2 helpers (SIMD f32, .rn rounding == scalar f32 exactly) ----
__device__ __forceinline__ unsigned long long pk2(float lo, float hi) {
    unsigned long long r;
    asm("mov.b64 %0, {%1, %2};" : "=l"(r)
        : "r"(__float_as_uint(lo)), "r"(__float_as_uint(hi)));
    return r;
}
__device__ __forceinline__ void upk2(unsigned long long v, float& lo, float& hi) {
    unsigned a, b;
    asm("mov.b64 {%0, %1}, %2;" : "=r"(a), "=r"(b) : "l"(v));
    lo = __uint_as_float(a); hi = __uint_as_float(b);
}
#define F2ADD(o, a, b) asm("add.rn.f32x2 %0, %1, %2;" : "=l"(o) : "l"(a), "l"(b))
#define F2MUL(o, a, b) asm("mul.rn.f32x2 %0, %1, %2;" : "=l"(o) : "l"(a), "l"(b))
#define F2FMA(o, a, b, c) asm("fma.rn.f32x2 %0, %1, %2, %3;" : "=l"(o) : "l"(a), "l"(b), "l"(c))

// ---------------------------------------------------------------------------
// Stage 1: FPS. (byte-identical to rounds 8/9: 356us measured)
// ---------------------------------------------------------------------------
__global__ __launch_bounds__(512, 1)
void fps_kernel(const float* __restrict__ xyz, float* __restrict__ new_xyz)
{
    extern __shared__ float sm[];
    float* xs = sm;
    float* ys = sm + NN;
    float* zs = sm + 2 * NN;
    __shared__ unsigned long long pairs[2][16];

    const int b   = blockIdx.x;
    const int tid = threadIdx.x;
    const int lane = tid & 31, wid = tid >> 5;

    const float* gx = xyz + (size_t)b * NN * 3;
    for (int j = tid; j < NN * 3; j += 512) {
        float v = gx[j];
        int p = j / 3, c = j - p * 3;
        if (c == 0) xs[p] = v; else if (c == 1) ys[p] = v; else zs[p] = v;
    }
    __syncthreads();

    const int base = tid * 8;
    unsigned long long pxx[4], pyy[4], pzz[4];
    float dd[8];
#pragma unroll
    for (int p = 0; p < 4; p++) {
        pxx[p] = pk2(xs[base + 2 * p], xs[base + 2 * p + 1]);
        pyy[p] = pk2(ys[base + 2 * p], ys[base + 2 * p + 1]);
        pzz[p] = pk2(zs[base + 2 * p], zs[base + 2 * p + 1]);
        dd[2 * p] = 1e10f; dd[2 * p + 1] = 1e10f;
    }

    int far = 0;
    for (int it = 0; it < NS; it++) {
        const float cx = xs[far], cy = ys[far], cz = zs[far];
        if (tid == 0) {
            float* o = new_xyz + ((size_t)b * NS + it) * 3;
            o[0] = cx; o[1] = cy; o[2] = cz;
        }
        const unsigned long long ncx = pk2(-cx, -cx);
        const unsigned long long ncy = pk2(-cy, -cy);
        const unsigned long long ncz = pk2(-cz, -cz);

        float lm = 0.0f;
        int lidx = 0;
#pragma unroll
        for (int p = 0; p < 4; p++) {
            unsigned long long dx, dy, dz, t;
            F2ADD(dx, pxx[p], ncx);
            F2ADD(dy, pyy[p], ncy);
            F2ADD(dz, pzz[p], ncz);
            F2MUL(t, dx, dx);
            F2FMA(t, dy, dy, t);
            F2FMA(t, dz, dz, t);
            float d0, d1; upk2(t, d0, d1);
            float n0 = fminf(dd[2 * p], d0);
            float n1 = fminf(dd[2 * p + 1], d1);
            dd[2 * p] = n0; dd[2 * p + 1] = n1;
            if (n0 > lm) { lm = n0; lidx = base + 2 * p; }
            if (n1 > lm) { lm = n1; lidx = base + 2 * p + 1; }
        }
        const unsigned lmb = __float_as_uint(lm);
        const unsigned wm  = __reduce_max_sync(0xffffffffu, lmb);
        const unsigned wix = __reduce_min_sync(0xffffffffu,
                                (lmb == wm) ? (unsigned)lidx : 0xffffffffu);
        if (lane == 0)
            pairs[it & 1][wid] = ((unsigned long long)wm << 32) | (4095u - wix);
        __syncthreads();
        const unsigned long long kk = (lane < 16) ? pairs[it & 1][lane] : 0ull;
        const unsigned hi = (unsigned)(kk >> 32);
        const unsigned mh = __reduce_max_sync(0xffffffffu, hi);
        const unsigned lo = (hi == mh) ? (unsigned)kk : 0u;
        const unsigned ml = __reduce_max_sync(0xffffffffu, lo);
        far = 4095 - (int)ml;
    }
}

// ---------------------------------------------------------------------------
// Stage 2: kNN, 4-way split scan. 4 threads per query, each scans a disjoint
// quarter (1024 candidates) into its own 32-key max-heap (u64 keys unique:
// mapped distbits<<32 | global idx). Hierarchical exact rank-merge:
//   stage A: pairs {0,1},{2,3} -> top-32 of each half-pair, materialized in
//            the dead cand[] region (exactly 64 KB for 128q x 64 keys).
//   stage B: 4 threads x 16 keys rank among the 64 -> g_idx[rank].
// Top-32 of union of per-part top-32s == exact top-32; key order == (dist,
// idx) == top_k tie rule. 512 thr/block, 128 blocks.
// ---------------------------------------------------------------------------
#define HEAP_STRIDE 33
#define QRT 1024
__global__ __launch_bounds__(512, 1)
void knn_kernel(const float* __restrict__ xyz, const float* __restrict__ new_xyz)
{
    extern __shared__ float4 cand[];                       // NN entries = 64 KB
    unsigned long long* heap =
        (unsigned long long*)(cand + NN);                  // 512*33*8 = 135 KB
    unsigned long long* merged = (unsigned long long*)cand; // reused after scan

    const int b     = blockIdx.x >> 3;         // 8 blocks of 128 queries per batch
    const int chunk = blockIdx.x & 7;
    const int tid   = threadIdx.x;
    const int qloc  = tid & 127;               // query within chunk
    const int half  = tid >> 7;                // candidate quarter 0..3

    const float* gx = xyz + (size_t)b * NN * 3;
    for (int p = tid; p < NN; p += 512) {
        float x = gx[p * 3], y = gx[p * 3 + 1], z = gx[p * 3 + 2];
        float psq = __fadd_rn(__fadd_rn(__fmul_rn(x, x), __fmul_rn(y, y)),
                              __fmul_rn(z, z));
        cand[p] = make_float4(x, y, z, psq);
    }

    unsigned long long* hp = heap + tid * HEAP_STRIDE;
#pragma unroll
    for (int t = 0; t < NK; t++) hp[t] = ~0ull;
    unsigned long long root = ~0ull;
    __syncthreads();

    const int s = chunk * 128 + qloc;
    const float* q = new_xyz + ((size_t)b * NS + s) * 3;
    const float qx = q[0], qy = q[1], qz = q[2];
    const float qsq = __fadd_rn(__fadd_rn(__fmul_rn(qx, qx), __fmul_rn(qy, qy)),
                                __fmul_rn(qz, qz));

    const int start = half * QRT;
    float4 c = cand[start];
    for (int i = 0; i < QRT; i++) {
        float4 nxt = cand[start + ((i + 1) & (QRT - 1))];   // prefetch
        const int j = start + i;
        float dot = __fadd_rn(__fadd_rn(__fmul_rn(qx, c.x), __fmul_rn(qy, c.y)),
                              __fmul_rn(qz, c.z));
        float sq = __fsub_rn(__fadd_rn(qsq, c.w), __fmul_rn(2.0f, dot));
        unsigned ub = __float_as_uint(sq);
        ub ^= ((unsigned)((int)ub >> 31)) | 0x80000000u;   // order-preserving map
        unsigned long long key = ((unsigned long long)ub << 32) | (unsigned)j;

        if (key < root) {
            int pos = 0;
#pragma unroll
            for (int lvl = 0; lvl < 5; lvl++) {
                int ch = 2 * pos + 1;
                if (ch >= NK) break;
                unsigned long long lk = hp[ch];
                unsigned long long rk = (ch + 1 < NK) ? hp[ch + 1] : 0ull;
                unsigned long long mk = (rk > lk) ? rk : lk;
                int mc = (rk > lk) ? ch + 1 : ch;
                if (mk <= key) break;
                hp[pos] = mk;
                if (lvl == 0) root = mk;
                pos = mc;
            }
            hp[pos] = key;
            if (pos == 0) root = key;
        }
        c = nxt;
    }
    __syncthreads();   // scan done; cand[] is dead, heaps live

    // stage A: pairwise rank-merge {0,1} and {2,3} -> merged[q][pair*32 + r]
    {
        const unsigned long long* hq = heap + (tid ^ 128) * HEAP_STRIDE;
        const int pairid = half >> 1;
        unsigned long long* mq = merged + (size_t)qloc * 64 + pairid * 32;
        // copy own keys to registers first (cand alias: hp is in heap, safe)
        unsigned long long mine[NK];
#pragma unroll
        for (int t = 0; t < NK; t++) mine[t] = hp[t];
#pragma unroll 4
        for (int i = 0; i < NK; i++) {
            const unsigned long long k = mine[i];
            int r = 0;
#pragma unroll 8
            for (int t = 0; t < NK; t++) r += (mine[t] < k);
#pragma unroll 8
            for (int t = 0; t < NK; t++) r += (hq[t] < k);
            if (r < NK) mq[r] = k;
        }
    }
    __syncthreads();

    // stage B: 16 keys per thread, rank among the 64 merged keys
    {
        const unsigned long long* mq = merged + (size_t)qloc * 64;
        int* outp = g_idx + ((size_t)b * NS + s) * NK;
#pragma unroll 4
        for (int i = 0; i < 16; i++) {
            const unsigned long long k = mq[half * 16 + i];
            int r = 0;
#pragma unroll 8
            for (int t = 0; t < 64; t++) r += (mq[t] < k);
            if (r < NK) outp[r] = (int)(k & 0xffffffffull);
        }
    }
}

// ---------------------------------------------------------------------------
// Stage 3: gather + 1x1 conv (67->128) + max over K + LayerNorm.
// (byte-identical to rounds 6-9)
// ---------------------------------------------------------------------------
#define FT_PITCH 40
#define QPB3 32
__global__ __launch_bounds__(128, 4)
void embed_kernel(const float* __restrict__ xyz, const float* __restrict__ voxels,
                  const float* __restrict__ w, const float* __restrict__ bias,
                  const float* __restrict__ gamma, const float* __restrict__ beta,
                  const float* __restrict__ new_xyz, float* __restrict__ out)
{
    __shared__ float wt[CIN * NOUT];        // [c][o]  34304 B
    __shared__ float ft[CIN * FT_PITCH];    // [c][k]  10720 B
    __shared__ float pm[4 * NOUT];          // [kg][o]  2048 B
    __shared__ float red[4];

    const int tid  = threadIdx.x;
    const int lane = tid & 31, wid = tid >> 5;
    const int og   = tid & 31;
    const int kg   = tid >> 5;
    const int k    = tid >> 2;
    const int quad = tid & 3;

    {
        const float* wrow = w + tid * CIN;
        for (int c = 0; c < CIN; c++)
            wt[c * NOUT + tid] = wrow[c];
    }
    float bs[4];
#pragma unroll
    for (int j = 0; j < 4; j++) bs[j] = bias[og * 4 + j];
    const float go = gamma[tid], be = beta[tid];

    for (int q = 0; q < QPB3; q++) {
        const int gq = blockIdx.x * QPB3 + q;
        const int b  = gq >> 10;

        __syncthreads();

        const int nidx = g_idx[(size_t)gq * NK + k];
        const float4* vrow = (const float4*)(voxels + ((size_t)b * NN + nidx) * NC);
#pragma unroll
        for (int i = 0; i < 4; i++) {
            float4 v = vrow[quad * 4 + i];
            const int cb = 3 + quad * 16 + i * 4;
            ft[(cb + 0) * FT_PITCH + k] = v.x;
            ft[(cb + 1) * FT_PITCH + k] = v.y;
            ft[(cb + 2) * FT_PITCH + k] = v.z;
            ft[(cb + 3) * FT_PITCH + k] = v.w;
        }
        if (quad == 0) {
            const float* prow = xyz + ((size_t)b * NN + nidx) * 3;
            const float* qrow = new_xyz + (size_t)gq * 3;
            ft[0 * FT_PITCH + k] = __fsub_rn(prow[0], qrow[0]);
            ft[1 * FT_PITCH + k] = __fsub_rn(prow[1], qrow[1]);
            ft[2 * FT_PITCH + k] = __fsub_rn(prow[2], qrow[2]);
        }
        __syncthreads();

        float a0[8], a1[8], a2[8], a3[8];
#pragma unroll
        for (int n = 0; n < 8; n++) { a0[n] = bs[0]; a1[n] = bs[1]; a2[n] = bs[2]; a3[n] = bs[3]; }

#pragma unroll 2
        for (int c = 0; c < CIN; c++) {
            float4 wv = *(const float4*)&wt[c * NOUT + og * 4];
            float4 f0 = *(const float4*)&ft[c * FT_PITCH + kg * 8];
            float4 f1 = *(const float4*)&ft[c * FT_PITCH + kg * 8 + 4];
            float fv[8] = {f0.x, f0.y, f0.z, f0.w, f1.x, f1.y, f1.z, f1.w};
#pragma unroll
            for (int n = 0; n < 8; n++) {
                a0[n] = fmaf(wv.x, fv[n], a0[n]);
                a1[n] = fmaf(wv.y, fv[n], a1[n]);
                a2[n] = fmaf(wv.z, fv[n], a2[n]);
                a3[n] = fmaf(wv.w, fv[n], a3[n]);
            }
        }

        float p0 = a0[0], p1 = a1[0], p2 = a2[0], p3 = a3[0];
#pragma unroll
        for (int n = 1; n < 8; n++) {
            p0 = fmaxf(p0, a0[n]); p1 = fmaxf(p1, a1[n]);
            p2 = fmaxf(p2, a2[n]); p3 = fmaxf(p3, a3[n]);
        }
        *(float4*)&pm[kg * NOUT + og * 4] = make_float4(p0, p1, p2, p3);
        __syncthreads();

        float m = fmaxf(fmaxf(pm[0 * NOUT + tid], pm[1 * NOUT + tid]),
                        fmaxf(pm[2 * NOUT + tid], pm[3 * NOUT + tid]));

        float v = m;
#pragma unroll
        for (int off = 16; off; off >>= 1) v += __shfl_xor_sync(0xffffffffu, v, off);
        if (lane == 0) red[wid] = v;
        __syncthreads();
        const float mu = (red[0] + red[1] + red[2] + red[3]) * (1.0f / 128.0f);
        const float dm = m - mu;
        __syncthreads();
        float v2 = dm * dm;
#pragma unroll
        for (int off = 16; off; off >>= 1) v2 += __shfl_xor_sync(0xffffffffu, v2, off);
        if (lane == 0) red[wid] = v2;
        __syncthreads();
        const float var = (red[0] + red[1] + red[2] + red[3]) * (1.0f / 128.0f);
        out[(size_t)gq * NOUT + tid] = dm * rsqrtf(var + 1e-5f) * go + be;
    }
}

// ---------------------------------------------------------------------------
extern "C" void kernel_launch(void* const* d_in, const int* in_sizes, int n_in,
                              void* d_out, int out_size)
{
    const float* xyz    = (const float*)d_in[0];
    const float* voxels = (const float*)d_in[1];
    const float* conv_w = (const float*)d_in[2];
    const float* conv_b = (const float*)d_in[3];
    const float* ln_g   = (const float*)d_in[4];
    const float* ln_b   = (const float*)d_in[5];

    float* out      = (float*)d_out;                    // [B, S, OUT]
    float* new_xyz  = out + (size_t)NB * NS * NOUT;     // [B, S, 3]

    const size_t knn_smem = NN * sizeof(float4)
                          + 512 * HEAP_STRIDE * sizeof(unsigned long long);

    cudaFuncSetAttribute(fps_kernel, cudaFuncAttributeMaxDynamicSharedMemorySize,
                         3 * NN * sizeof(float));
    cudaFuncSetAttribute(knn_kernel, cudaFuncAttributeMaxDynamicSharedMemorySize,
                         (int)knn_smem);

    fps_kernel<<<NB, 512, 3 * NN * sizeof(float)>>>(xyz, new_xyz);
    knn_kernel<<<NB * 8, 512, knn_smem>>>(xyz, new_xyz);
    embed_kernel<<<(NB * NS) / QPB3, 128>>>(xyz, voxels, conv_w, conv_b,
                                            ln_g, ln_b, new_xyz, out);
}